// round 14
// baseline (speedup 1.0000x reference)
#include <cuda_runtime.h>
#include <cuda_bf16.h>
#include <cstdint>

__device__ double g_acc = 0.0;
__device__ unsigned int g_done = 0;

#define WPB    8            // warps per block
#define TPB    (WPB * 32)
#define STAGES 3            // cp.async ring depth per warp
#define STAGE_F4 96         // 32 groups * 3 float4 per stage

__global__ void __launch_bounds__(TPB, 6)
imputation_loss_kernel(const float* __restrict__ logits,
                       const int*   __restrict__ targets,
                       float* __restrict__ out,
                       int n, int fullGroups, int chunksTotal, int chunksFull,
                       int gridBlocks) {
    __shared__ float4 buf[WPB][STAGES * STAGE_F4];      // 36 KB
    const float4* lp = reinterpret_cast<const float4*>(logits);
    const int4*   tp = reinterpret_cast<const int4*>(targets);
    const int totalF4 = fullGroups * 3;

    int lane = threadIdx.x & 31;
    int wid  = threadIdx.x >> 5;
    int totalWarps = gridBlocks * WPB;
    int myChunk = blockIdx.x * WPB + wid;
    float local = 0.0f;

    uint32_t wbase = (uint32_t)__cvta_generic_to_shared(&buf[wid][0]);

    // issue one stage's copies; fast path = no per-element bounds checks
    auto issue_stage = [&](int ck, int stage) {
        uint32_t dst = wbase + (uint32_t)stage * (STAGE_F4 * 16) + (uint32_t)lane * 16;
        if (ck < chunksFull) {
            const float4* src = lp + (size_t)((unsigned)ck * 96u + (unsigned)lane);
            asm volatile("cp.async.cg.shared.global [%0], [%1], 16;" :: "r"(dst),        "l"(src)      : "memory");
            asm volatile("cp.async.cg.shared.global [%0], [%1], 16;" :: "r"(dst + 512),  "l"(src + 32) : "memory");
            asm volatile("cp.async.cg.shared.global [%0], [%1], 16;" :: "r"(dst + 1024), "l"(src + 64) : "memory");
        } else if (ck < chunksTotal) {
            int fb = ck * 96;
            #pragma unroll
            for (int k = 0; k < 3; ++k) {
                int idx = fb + lane + 32 * k;
                const float4* src = (idx < totalF4) ? (lp + idx) : lp;
                int sz = (idx < totalF4) ? 16 : 0;
                asm volatile("cp.async.cg.shared.global [%0], [%1], 16, %2;"
                             :: "r"(dst + k * 512), "l"(src), "r"(sz) : "memory");
            }
        }
        asm volatile("cp.async.commit_group;" ::: "memory");
    };

    // group math: 4 rows, softmax relative to each row's l0, Montgomery batch rcp.
    auto group_accum = [&](float4 a, float4 b, float4 cc, int4 t4) {
        float u0 = __expf(a.y - a.x),   v0 = __expf(a.z - a.x);
        float u1 = __expf(b.x - a.w),   v1 = __expf(b.y - a.w);
        float u2 = __expf(b.w - b.z),   v2 = __expf(cc.x - b.z);
        float u3 = __expf(cc.z - cc.y), v3 = __expf(cc.w - cc.y);
        float s0 = 1.0f + u0 + v0;
        float s1 = 1.0f + u1 + v1;
        float s2 = 1.0f + u2 + v2;
        float s3 = 1.0f + u3 + v3;

        float lin = 0.0f;
        lin += a.x  - ((t4.x == 0) ? a.x  : ((t4.x == 1) ? a.y  : a.z));
        lin += a.w  - ((t4.y == 0) ? a.w  : ((t4.y == 1) ? b.x  : b.y));
        lin += b.z  - ((t4.z == 0) ? b.z  : ((t4.z == 1) ? b.w  : cc.x));
        lin += cc.y - ((t4.w == 0) ? cc.y : ((t4.w == 1) ? cc.z : cc.w));
        int k1 = ((t4.x == 1) ? 1 : 0) + ((t4.y == 1) ? 1 : 0)
               + ((t4.z == 1) ? 1 : 0) + ((t4.w == 1) ? 1 : 0);

        // 1 RCP for 4 reciprocals; p3 doubles as the deferred-log argument.
        float p1 = s0 * s1;
        float p2 = p1 * s2;
        float p3 = p2 * s3;               // <= ~6e18, finite
        float r;
        asm("rcp.approx.ftz.f32 %0, %1;" : "=f"(r) : "f"(p3));
        float inv3 = r * p2;   r *= s3;
        float inv2 = r * p1;   r *= s2;
        float inv1 = r * s0;
        float inv0 = r * s1;

        float d0 = 0.5f - inv0, d1 = 0.5f - inv1;
        float d2 = 0.5f - inv2, d3 = 0.5f - inv3;
        float ssq = d0*d0 + d1*d1 + d2*d2 + d3*d3;

        // CE = lin + log(p3); group R2 = -(ssq/cnt)/0.25*cnt*k1 = -4*ssq*k1
        local += lin + __logf(p3) - 4.0f * ssq * (float)k1;
    };

    // one steady iteration; consume slot and refill slot are compile-time.
    // Consume sequence walks stages 0,1,2,0,...; the chunk issued here (ck+2W)
    // is consumed two iterations later, i.e. at slot (stage+2)%3.
    auto steady_iter = [&](int ck, int cstage, int rstage) {
        int4 t4 = __ldcs(tp + (size_t)((unsigned)ck * 32u + (unsigned)lane));

        asm volatile("cp.async.wait_group %0;" :: "n"(STAGES - 2) : "memory");
        __syncwarp();

        const float4* s4 = &buf[wid][cstage * STAGE_F4];
        float4 a  = s4[3 * lane + 0];       // 48B lane stride: conflict-free
        float4 b  = s4[3 * lane + 1];
        float4 cc = s4[3 * lane + 2];

        issue_stage(ck + (STAGES - 1) * totalWarps, rstage);

        group_accum(a, b, cc, t4);
    };

    // prologue: stages 0..STAGES-2 in flight
    #pragma unroll
    for (int s = 0; s < STAGES - 1; ++s)
        issue_stage(myChunk + s * totalWarps, s);

    int ck = myChunk;

    // unrolled steady loop: 3 chunks per trip; consume 0,1,2 ; refill 2,0,1.
    for (; ck + 2 * totalWarps < chunksFull; ck += 3 * totalWarps) {
        steady_iter(ck,                  0, 2);
        steady_iter(ck +     totalWarps, 1, 0);
        steady_iter(ck + 2 * totalWarps, 2, 1);
    }

    // steady remainder (0..2 chunks), runtime stage index; next consume slot is 0
    int sb = 0;
    for (; ck < chunksFull; ck += totalWarps) {
        int4 t4 = __ldcs(tp + (size_t)((unsigned)ck * 32u + (unsigned)lane));
        asm volatile("cp.async.wait_group %0;" :: "n"(STAGES - 2) : "memory");
        __syncwarp();
        const float4* s4 = &buf[wid][sb * STAGE_F4];
        float4 a  = s4[3 * lane + 0];
        float4 b  = s4[3 * lane + 1];
        float4 cc = s4[3 * lane + 2];
        int rstage = sb + (STAGES - 1); if (rstage >= STAGES) rstage -= STAGES;
        issue_stage(ck + (STAGES - 1) * totalWarps, rstage);
        group_accum(a, b, cc, t4);
        if (++sb == STAGES) sb = 0;
    }

    // fringe: final partially-filled chunk(s), guarded (empty when n % 128 == 0)
    for (; ck < chunksTotal; ck += totalWarps) {
        asm volatile("cp.async.wait_group %0;" :: "n"(STAGES - 2) : "memory");
        __syncwarp();
        int g = ck * 32 + lane;
        int4 t4 = {0, 0, 0, 0};
        if (g < fullGroups) t4 = __ldcs(tp + g);
        const float4* s4 = &buf[wid][sb * STAGE_F4];
        float4 a  = s4[3 * lane + 0];
        float4 b  = s4[3 * lane + 1];
        float4 cc = s4[3 * lane + 2];
        int rstage = sb + (STAGES - 1); if (rstage >= STAGES) rstage -= STAGES;
        issue_stage(ck + (STAGES - 1) * totalWarps, rstage);
        if (g < fullGroups) group_accum(a, b, cc, t4);
        if (++sb == STAGES) sb = 0;
    }

    // Row-tail beyond full groups (n % 4 rows): one thread; cnt cancels.
    if (blockIdx.x == 0 && threadIdx.x == 0 && fullGroups * 4 < n) {
        float lin = 0.0f, prod = 1.0f, ssq = 0.0f; int k1 = 0;
        for (int i = fullGroups * 4; i < n; ++i) {
            float l0 = logits[3*i], l1 = logits[3*i+1], l2 = logits[3*i+2];
            int t = targets[i];
            float u = __expf(l1 - l0), v = __expf(l2 - l0);
            float s = 1.0f + u + v;
            float rs = 1.0f / s;
            float lt = (t == 0) ? l0 : ((t == 1) ? l1 : l2);
            lin += l0 - lt; prod *= s;
            float d = 0.5f - rs; ssq += d * d;
            k1 += (t == 1) ? 1 : 0;
        }
        local += lin + __logf(prod) - 4.0f * ssq * (float)k1;
    }

    // block reduction in double
    double vv = (double)local;
    #pragma unroll
    for (int o = 16; o; o >>= 1) vv += __shfl_down_sync(0xffffffffu, vv, o);
    __shared__ double ws[WPB];
    if (lane == 0) ws[wid] = vv;
    __syncthreads();
    if (wid == 0) {
        vv = (lane < WPB) ? ws[lane] : 0.0;
        #pragma unroll
        for (int o = 16; o; o >>= 1) vv += __shfl_down_sync(0xffffffffu, vv, o);
        if (lane == 0) {
            atomicAdd(&g_acc, vv);
            __threadfence();
            unsigned int done = atomicAdd(&g_done, 1u);
            if (done == (unsigned)gridBlocks - 1u) {
                double total = atomicAdd(&g_acc, 0.0);
                out[0] = (float)total;
                g_acc  = 0.0;
                g_done = 0;
            }
        }
    }
}

extern "C" void kernel_launch(void* const* d_in, const int* in_sizes, int n_in,
                              void* d_out, int out_size) {
    const float* logits  = (const float*)d_in[0];
    const int*   targets = (const int*)d_in[1];
    float* out = (float*)d_out;
    int n = in_sizes[1];
    int fullGroups  = n / 4;
    int chunksTotal = (fullGroups + 31) / 32;      // 32 groups per warp-chunk
    int chunksFull  = fullGroups / 32;             // chunks with all 32 groups valid
    int blocks = 148 * 6;                          // 6 blocks/SM (smem-limited)
    int maxUseful = (chunksTotal + WPB - 1) / WPB;
    if (blocks > maxUseful) blocks = maxUseful;
    if (blocks < 1) blocks = 1;
    imputation_loss_kernel<<<blocks, TPB>>>(logits, targets, out,
                                            n, fullGroups, chunksTotal, chunksFull,
                                            blocks);
}

// round 15
// speedup vs baseline: 1.0169x; 1.0169x over previous
#include <cuda_runtime.h>
#include <cuda_bf16.h>
#include <cstdint>

__device__ double g_acc = 0.0;
__device__ unsigned int g_done = 0;

#define WPB    8            // warps per block
#define TPB    (WPB * 32)
#define STAGES 3            // cp.async ring depth per warp
#define STAGE_F4 96         // 32 groups * 3 float4 per stage

__global__ void __launch_bounds__(TPB, 6)
imputation_loss_kernel(const float* __restrict__ logits,
                       const int*   __restrict__ targets,
                       float* __restrict__ out,
                       int n, int fullGroups, int chunksTotal, int chunksFull,
                       int gridBlocks) {
    __shared__ float4 buf[WPB][STAGES * STAGE_F4];      // 36 KB
    const float4* lp = reinterpret_cast<const float4*>(logits);
    const int4*   tp = reinterpret_cast<const int4*>(targets);
    const int totalF4 = fullGroups * 3;

    int lane = threadIdx.x & 31;
    int wid  = threadIdx.x >> 5;
    int totalWarps = gridBlocks * WPB;
    int myChunk = blockIdx.x * WPB + wid;
    float local = 0.0f;

    uint32_t wbase = (uint32_t)__cvta_generic_to_shared(&buf[wid][0]);

    // issue one stage's copies; fast path = no per-element bounds checks
    auto issue_stage = [&](int ck, int stage) {
        uint32_t dst = wbase + (uint32_t)stage * (STAGE_F4 * 16) + (uint32_t)lane * 16;
        if (ck < chunksFull) {
            const float4* src = lp + (size_t)((unsigned)ck * 96u + (unsigned)lane);
            asm volatile("cp.async.cg.shared.global [%0], [%1], 16;" :: "r"(dst),        "l"(src)      : "memory");
            asm volatile("cp.async.cg.shared.global [%0], [%1], 16;" :: "r"(dst + 512),  "l"(src + 32) : "memory");
            asm volatile("cp.async.cg.shared.global [%0], [%1], 16;" :: "r"(dst + 1024), "l"(src + 64) : "memory");
        } else if (ck < chunksTotal) {
            int fb = ck * 96;
            #pragma unroll
            for (int k = 0; k < 3; ++k) {
                int idx = fb + lane + 32 * k;
                const float4* src = (idx < totalF4) ? (lp + idx) : lp;
                int sz = (idx < totalF4) ? 16 : 0;
                asm volatile("cp.async.cg.shared.global [%0], [%1], 16, %2;"
                             :: "r"(dst + k * 512), "l"(src), "r"(sz) : "memory");
            }
        }
        asm volatile("cp.async.commit_group;" ::: "memory");
    };

    // group math: 4 rows, softmax relative to each row's l0, Montgomery batch rcp.
    auto group_accum = [&](float4 a, float4 b, float4 cc, int4 t4) {
        float u0 = __expf(a.y - a.x),   v0 = __expf(a.z - a.x);
        float u1 = __expf(b.x - a.w),   v1 = __expf(b.y - a.w);
        float u2 = __expf(b.w - b.z),   v2 = __expf(cc.x - b.z);
        float u3 = __expf(cc.z - cc.y), v3 = __expf(cc.w - cc.y);
        float s0 = 1.0f + u0 + v0;
        float s1 = 1.0f + u1 + v1;
        float s2 = 1.0f + u2 + v2;
        float s3 = 1.0f + u3 + v3;

        float lin = 0.0f;
        lin += a.x  - ((t4.x == 0) ? a.x  : ((t4.x == 1) ? a.y  : a.z));
        lin += a.w  - ((t4.y == 0) ? a.w  : ((t4.y == 1) ? b.x  : b.y));
        lin += b.z  - ((t4.z == 0) ? b.z  : ((t4.z == 1) ? b.w  : cc.x));
        lin += cc.y - ((t4.w == 0) ? cc.y : ((t4.w == 1) ? cc.z : cc.w));
        int k1 = ((t4.x == 1) ? 1 : 0) + ((t4.y == 1) ? 1 : 0)
               + ((t4.z == 1) ? 1 : 0) + ((t4.w == 1) ? 1 : 0);

        // 1 RCP for 4 reciprocals; p3 doubles as the deferred-log argument.
        float p1 = s0 * s1;
        float p2 = p1 * s2;
        float p3 = p2 * s3;               // <= ~6e18, finite
        float r;
        asm("rcp.approx.ftz.f32 %0, %1;" : "=f"(r) : "f"(p3));
        float inv3 = r * p2;   r *= s3;
        float inv2 = r * p1;   r *= s2;
        float inv1 = r * s0;
        float inv0 = r * s1;

        float d0 = 0.5f - inv0, d1 = 0.5f - inv1;
        float d2 = 0.5f - inv2, d3 = 0.5f - inv3;
        float ssq = d0*d0 + d1*d1 + d2*d2 + d3*d3;

        // CE = lin + log(p3); group R2 = -(ssq/cnt)/0.25*cnt*k1 = -4*ssq*k1
        local += lin + __logf(p3) - 4.0f * ssq * (float)k1;
    };

    // one steady iteration; consume slot and refill slot are compile-time.
    // Consume sequence walks stages 0,1,2,0,...; the chunk issued here (ck+2W)
    // is consumed two iterations later, i.e. at slot (stage+2)%3.
    auto steady_iter = [&](int ck, int cstage, int rstage) {
        int4 t4 = __ldcs(tp + (size_t)((unsigned)ck * 32u + (unsigned)lane));

        asm volatile("cp.async.wait_group %0;" :: "n"(STAGES - 2) : "memory");
        __syncwarp();

        const float4* s4 = &buf[wid][cstage * STAGE_F4];
        float4 a  = s4[3 * lane + 0];       // 48B lane stride: conflict-free
        float4 b  = s4[3 * lane + 1];
        float4 cc = s4[3 * lane + 2];

        issue_stage(ck + (STAGES - 1) * totalWarps, rstage);

        group_accum(a, b, cc, t4);
    };

    // prologue: stages 0..STAGES-2 in flight
    #pragma unroll
    for (int s = 0; s < STAGES - 1; ++s)
        issue_stage(myChunk + s * totalWarps, s);

    int ck = myChunk;

    // unrolled steady loop: 3 chunks per trip; consume 0,1,2 ; refill 2,0,1.
    for (; ck + 2 * totalWarps < chunksFull; ck += 3 * totalWarps) {
        steady_iter(ck,                  0, 2);
        steady_iter(ck +     totalWarps, 1, 0);
        steady_iter(ck + 2 * totalWarps, 2, 1);
    }

    // steady remainder (0..2 chunks), runtime stage index; next consume slot is 0
    int sb = 0;
    for (; ck < chunksFull; ck += totalWarps) {
        int4 t4 = __ldcs(tp + (size_t)((unsigned)ck * 32u + (unsigned)lane));
        asm volatile("cp.async.wait_group %0;" :: "n"(STAGES - 2) : "memory");
        __syncwarp();
        const float4* s4 = &buf[wid][sb * STAGE_F4];
        float4 a  = s4[3 * lane + 0];
        float4 b  = s4[3 * lane + 1];
        float4 cc = s4[3 * lane + 2];
        int rstage = sb + (STAGES - 1); if (rstage >= STAGES) rstage -= STAGES;
        issue_stage(ck + (STAGES - 1) * totalWarps, rstage);
        group_accum(a, b, cc, t4);
        if (++sb == STAGES) sb = 0;
    }

    // fringe: final partially-filled chunk(s), guarded (empty when n % 128 == 0)
    for (; ck < chunksTotal; ck += totalWarps) {
        asm volatile("cp.async.wait_group %0;" :: "n"(STAGES - 2) : "memory");
        __syncwarp();
        int g = ck * 32 + lane;
        int4 t4 = {0, 0, 0, 0};
        if (g < fullGroups) t4 = __ldcs(tp + g);
        const float4* s4 = &buf[wid][sb * STAGE_F4];
        float4 a  = s4[3 * lane + 0];
        float4 b  = s4[3 * lane + 1];
        float4 cc = s4[3 * lane + 2];
        int rstage = sb + (STAGES - 1); if (rstage >= STAGES) rstage -= STAGES;
        issue_stage(ck + (STAGES - 1) * totalWarps, rstage);
        if (g < fullGroups) group_accum(a, b, cc, t4);
        if (++sb == STAGES) sb = 0;
    }

    // Row-tail beyond full groups (n % 4 rows): one thread; cnt cancels.
    if (blockIdx.x == 0 && threadIdx.x == 0 && fullGroups * 4 < n) {
        float lin = 0.0f, prod = 1.0f, ssq = 0.0f; int k1 = 0;
        for (int i = fullGroups * 4; i < n; ++i) {
            float l0 = logits[3*i], l1 = logits[3*i+1], l2 = logits[3*i+2];
            int t = targets[i];
            float u = __expf(l1 - l0), v = __expf(l2 - l0);
            float s = 1.0f + u + v;
            float rs = 1.0f / s;
            float lt = (t == 0) ? l0 : ((t == 1) ? l1 : l2);
            lin += l0 - lt; prod *= s;
            float d = 0.5f - rs; ssq += d * d;
            k1 += (t == 1) ? 1 : 0;
        }
        local += lin + __logf(prod) - 4.0f * ssq * (float)k1;
    }

    // block reduction in double
    double vv = (double)local;
    #pragma unroll
    for (int o = 16; o; o >>= 1) vv += __shfl_down_sync(0xffffffffu, vv, o);
    __shared__ double ws[WPB];
    if (lane == 0) ws[wid] = vv;
    __syncthreads();
    if (wid == 0) {
        vv = (lane < WPB) ? ws[lane] : 0.0;
        #pragma unroll
        for (int o = 16; o; o >>= 1) vv += __shfl_down_sync(0xffffffffu, vv, o);
        if (lane == 0) {
            atomicAdd(&g_acc, vv);
            __threadfence();
            unsigned int done = atomicAdd(&g_done, 1u);
            if (done == (unsigned)gridBlocks - 1u) {
                double total = atomicAdd(&g_acc, 0.0);
                out[0] = (float)total;
                g_acc  = 0.0;
                g_done = 0;
            }
        }
    }
}

extern "C" void kernel_launch(void* const* d_in, const int* in_sizes, int n_in,
                              void* d_out, int out_size) {
    const float* logits  = (const float*)d_in[0];
    const int*   targets = (const int*)d_in[1];
    float* out = (float*)d_out;
    int n = in_sizes[1];
    int fullGroups  = n / 4;
    int chunksTotal = (fullGroups + 31) / 32;      // 32 groups per warp-chunk
    int chunksFull  = fullGroups / 32;             // chunks with all 32 groups valid
    int blocks = 148 * 6;                          // 6 blocks/SM (smem-limited)
    int maxUseful = (chunksTotal + WPB - 1) / WPB;
    if (blocks > maxUseful) blocks = maxUseful;
    if (blocks < 1) blocks = 1;
    imputation_loss_kernel<<<blocks, TPB>>>(logits, targets, out,
                                            n, fullGroups, chunksTotal, chunksFull,
                                            blocks);
}